// round 13
// baseline (speedup 1.0000x reference)
#include <cuda_runtime.h>
#include <cuda_fp16.h>
#include <cstdint>
#include <cstddef>

#define S_DIM 4096
#define D_DIM 1024

// ---------------- scratch (static device globals; no allocation) -------------
__device__ __half g_xh  [(size_t)S_DIM * D_DIM];
__device__ __half g_Wcat[(size_t)3 * D_DIM * D_DIM];   // [3072,1024] concat Wq^T,Wk^T,Wv^T
__device__ __half g_Qh  [(size_t)S_DIM * D_DIM];
__device__ __half g_Kh  [(size_t)S_DIM * D_DIM];
__device__ __half g_Vh  [(size_t)S_DIM * D_DIM];
__device__ __half g_Sh  [(size_t)S_DIM * S_DIM];       // exp(scores)
__device__ float  g_rs  [S_DIM];                       // row sums of exp(scores)

// ---------------- helpers ----------------------------------------------------
__device__ __forceinline__ uint32_t smem_u32(const void* p) {
    return (uint32_t)__cvta_generic_to_shared(p);
}
__device__ __forceinline__ void cp16(uint32_t dst, const void* src) {
    asm volatile("cp.async.cg.shared.global [%0], [%1], 16;" :: "r"(dst), "l"(src));
}
__device__ __forceinline__ void ldsm_x4(uint32_t& r0, uint32_t& r1,
                                        uint32_t& r2, uint32_t& r3, uint32_t a) {
    asm volatile("ldmatrix.sync.aligned.m8n8.x4.shared.b16 {%0,%1,%2,%3}, [%4];"
                 : "=r"(r0), "=r"(r1), "=r"(r2), "=r"(r3) : "r"(a));
}
__device__ __forceinline__ void ldsm_x4_t(uint32_t& r0, uint32_t& r1,
                                          uint32_t& r2, uint32_t& r3, uint32_t a) {
    asm volatile("ldmatrix.sync.aligned.m8n8.x4.trans.shared.b16 {%0,%1,%2,%3}, [%4];"
                 : "=r"(r0), "=r"(r1), "=r"(r2), "=r"(r3) : "r"(a));
}
__device__ __forceinline__ void mma16816(float* c, const uint32_t* a, const uint32_t* b) {
    asm volatile(
        "mma.sync.aligned.m16n8k16.row.col.f32.f16.f16.f32 "
        "{%0,%1,%2,%3}, {%4,%5,%6,%7}, {%8,%9}, {%0,%1,%2,%3};"
        : "+f"(c[0]), "+f"(c[1]), "+f"(c[2]), "+f"(c[3])
        : "r"(a[0]), "r"(a[1]), "r"(a[2]), "r"(a[3]), "r"(b[0]), "r"(b[1]));
}
__device__ __forceinline__ void red2f(float* p, float a, float b) {
    asm volatile("red.global.add.v2.f32 [%0], {%1, %2};" :: "l"(p), "f"(a), "f"(b) : "memory");
}

// Swizzled byte offset of a 16B segment (row, kseg) in a [rows x 32half] tile.
__device__ __forceinline__ uint32_t tswz(int row, int kseg) {
    return (uint32_t)((row >> 1) * 128 + (row & 1) * 64 +
                      ((((row >> 1) ^ kseg) & 3) << 4));
}

// ---------------- fp16 tensor-core GEMM ---------------------------------------
// MODE 0: C[M,N] += A[M,K-slice] @ B[K,N] (B row-major, trans path), fp32 out,
//         rows scaled by 1/RS[row], split-K over blockIdx.z via red.v2. (PV)
// MODE 2: C = A @ Bt^T, QKV routing - fp16 out to C0/C1/C2 by col0>>10.
// MODE 3: C = A @ Bt^T, fp16 exp(out) + atomic row-sum into RS.      (scores)
#define BKH 32
#define TILE_BYTES 8192            // A: 128r*32k*2B ; B: 32k*128n*2B (same size)
#define STAGE_BYTES (2 * TILE_BYTES)
#define NST 4
#define GSMEM (NST * STAGE_BYTES)  // 64 KB
#define KSPLIT 3

template <int MODE>
__global__ __launch_bounds__(128, 2) void gemm_f16(
    const __half* __restrict__ A, const __half* __restrict__ Bt,
    void* __restrict__ C0, void* __restrict__ C1, void* __restrict__ C2,
    float* __restrict__ RS, int M, int N, int K)
{
    extern __shared__ char smem[];
    const uint32_t sbase = smem_u32(smem);

    const int tid  = threadIdx.x;
    const int warp = tid >> 5;
    const int lane = tid & 31;
    const int warp_m = warp & 1;    // 2 warps x 64 rows
    const int warp_n = warp >> 1;   // 2 warps x 64 cols
    const int row0 = blockIdx.y * 128;
    const int col0 = blockIdx.x * 128;
    const int NC = K / BKH;

    // K-chunk range (split-K for MODE 0)
    int kc0 = 0, kc1 = NC;
    if (MODE == 0) {
        int per = (NC + KSPLIT - 1) / KSPLIT;
        kc0 = blockIdx.z * per;
        kc1 = kc0 + per; if (kc1 > NC) kc1 = NC;
    }

    float acc[4][8][4];
    #pragma unroll
    for (int mt = 0; mt < 4; mt++)
        #pragma unroll
        for (int nt = 0; nt < 8; nt++)
            #pragma unroll
            for (int i = 0; i < 4; i++) acc[mt][nt][i] = 0.0f;

    // ---- per-thread cp.async slots ----
    uint32_t sA[4], sB[4];
    const __half *gA[4], *gB[4];
    #pragma unroll
    for (int p = 0; p < 4; p++) {
        int u = tid + p * 128;
        int r = u >> 2, ks = u & 3;
        sA[p] = tswz(r, ks);
        gA[p] = A + (size_t)(row0 + r) * K + ks * 8;
        if (MODE == 0) {
            int br = u >> 4, nb = u & 15;            // br 0..31, nb 0..15
            sB[p] = TILE_BYTES + br * 256 + ((nb ^ (br & 7)) << 4);
            gB[p] = Bt + (size_t)br * N + col0 + nb * 8;
        } else {
            int br = u >> 2, ks2 = u & 3;
            sB[p] = TILE_BYTES + tswz(br, ks2);
            gB[p] = Bt + (size_t)(col0 + br) * K + ks2 * 8;
        }
    }

    auto load_chunk = [&](int c, int buf) {
        uint32_t base = sbase + buf * STAGE_BYTES;
        size_t offA = (size_t)c * BKH;
        #pragma unroll
        for (int p = 0; p < 4; p++) cp16(base + sA[p], gA[p] + offA);
        if (MODE == 0) {
            size_t offB = (size_t)c * BKH * N;
            #pragma unroll
            for (int p = 0; p < 4; p++) cp16(base + sB[p], gB[p] + offB);
        } else {
            #pragma unroll
            for (int p = 0; p < 4; p++) cp16(base + sB[p], gB[p] + offA);
        }
        asm volatile("cp.async.commit_group;");
    };

    // ---- precomputed fragment offsets (relative to stage base) ----
    const int lr = lane & 15;
    const int lk = lane >> 4;
    const uint32_t b0_row_off = (uint32_t)(lane & 15) * 256;
    const int b0_xor = lane & 7;
    const int b0_hi = lane >> 4;

    uint32_t aoff[2][4], boff[2][4];
    #pragma unroll
    for (int ks = 0; ks < 2; ks++) {
        #pragma unroll
        for (int mt = 0; mt < 4; mt++)
            aoff[ks][mt] = tswz(warp_m * 64 + mt * 16 + lr, ks * 2 + lk);
        #pragma unroll
        for (int np = 0; np < 4; np++) {
            if (MODE == 0) {
                int n16 = warp_n * 8 + np * 2 + b0_hi;
                boff[ks][np] = TILE_BYTES + ks * 4096 + b0_row_off +
                               (uint32_t)((n16 ^ b0_xor) << 4);
            } else {
                boff[ks][np] = TILE_BYTES + tswz(warp_n * 64 + np * 16 + lr, ks * 2 + lk);
            }
        }
    }

    // ---- prologue: 3 chunks in flight ----
    #pragma unroll
    for (int i = 0; i < 3; i++)
        if (kc0 + i < kc1) load_chunk(kc0 + i, i);

    // ---- mainloop: ONE barrier per chunk ----
    for (int c = kc0; c < kc1; c++) {
        int buf = (c - kc0) & 3;
        int wg = kc1 - 1 - c; if (wg > 2) wg = 2;
        if      (wg == 0) asm volatile("cp.async.wait_group 0;");
        else if (wg == 1) asm volatile("cp.async.wait_group 1;");
        else              asm volatile("cp.async.wait_group 2;");
        __syncthreads();
        // refill the buffer freed by iter c-1 (safe: everyone passed the barrier)
        if (c + 3 < kc1) load_chunk(c + 3, (c - kc0 + 3) & 3);

        uint32_t base = sbase + buf * STAGE_BYTES;

        #pragma unroll
        for (int ks = 0; ks < 2; ks++) {
            uint32_t af[4][4], blo[8], bhi[8];
            #pragma unroll
            for (int mt = 0; mt < 4; mt++)
                ldsm_x4(af[mt][0], af[mt][1], af[mt][2], af[mt][3], base + aoff[ks][mt]);
            if (MODE == 0) {
                #pragma unroll
                for (int np = 0; np < 4; np++)
                    ldsm_x4_t(blo[2 * np], bhi[2 * np],
                              blo[2 * np + 1], bhi[2 * np + 1], base + boff[ks][np]);
            } else {
                #pragma unroll
                for (int np = 0; np < 4; np++)
                    ldsm_x4(blo[2 * np], blo[2 * np + 1], bhi[2 * np], bhi[2 * np + 1],
                            base + boff[ks][np]);
            }
            #pragma unroll
            for (int mt = 0; mt < 4; mt++)
                #pragma unroll
                for (int nt = 0; nt < 8; nt++) {
                    uint32_t bf[2] = { blo[nt], bhi[nt] };
                    mma16816(acc[mt][nt], af[mt], bf);
                }
        }
    }

    // ---- epilogue ----
    const int g = lane >> 2, t = lane & 3;

    if (MODE == 2) {
        int sel = col0 >> 10;
        __half* Ch = (__half*)(sel == 0 ? C0 : sel == 1 ? C1 : C2);
        int cbase = (col0 & 1023) + warp_n * 64;
        #pragma unroll
        for (int mt = 0; mt < 4; mt++) {
            int r = row0 + warp_m * 64 + mt * 16 + g;
            #pragma unroll
            for (int nt = 0; nt < 8; nt++) {
                int cc = cbase + nt * 8 + t * 2;
                *reinterpret_cast<__half2*>(&Ch[(size_t)r * 1024 + cc]) =
                    __floats2half2_rn(acc[mt][nt][0], acc[mt][nt][1]);
                *reinterpret_cast<__half2*>(&Ch[(size_t)(r + 8) * 1024 + cc]) =
                    __floats2half2_rn(acc[mt][nt][2], acc[mt][nt][3]);
            }
        }
    } else if (MODE == 3) {
        __half* Ch = (__half*)C0;
        int cbase = col0 + warp_n * 64;
        #pragma unroll
        for (int mt = 0; mt < 4; mt++) {
            int r = row0 + warp_m * 64 + mt * 16 + g;
            float s0 = 0.0f, s1 = 0.0f;
            #pragma unroll
            for (int nt = 0; nt < 8; nt++) {
                int cc = cbase + nt * 8 + t * 2;
                float e0 = __expf(acc[mt][nt][0]);
                float e1 = __expf(acc[mt][nt][1]);
                float e2 = __expf(acc[mt][nt][2]);
                float e3 = __expf(acc[mt][nt][3]);
                s0 += e0 + e1;
                s1 += e2 + e3;
                *reinterpret_cast<__half2*>(&Ch[(size_t)r * N + cc]) =
                    __floats2half2_rn(e0, e1);
                *reinterpret_cast<__half2*>(&Ch[(size_t)(r + 8) * N + cc]) =
                    __floats2half2_rn(e2, e3);
            }
            s0 += __shfl_xor_sync(0xffffffffu, s0, 1);
            s0 += __shfl_xor_sync(0xffffffffu, s0, 2);
            s1 += __shfl_xor_sync(0xffffffffu, s1, 1);
            s1 += __shfl_xor_sync(0xffffffffu, s1, 2);
            if (t == 0) {
                atomicAdd(&RS[r], s0);
                atomicAdd(&RS[r + 8], s1);
            }
        }
    } else {
        // MODE 0: split-K partial, scaled by 1/rowsum, accumulated via red.v2
        float* Cf = (float*)C0;
        int cbase = col0 + warp_n * 64;
        #pragma unroll
        for (int mt = 0; mt < 4; mt++) {
            int r = row0 + warp_m * 64 + mt * 16 + g;
            float i0 = 1.0f / RS[r];
            float i1 = 1.0f / RS[r + 8];
            #pragma unroll
            for (int nt = 0; nt < 8; nt++) {
                int cc = cbase + nt * 8 + t * 2;
                red2f(&Cf[(size_t)r * N + cc],       acc[mt][nt][0] * i0, acc[mt][nt][1] * i0);
                red2f(&Cf[(size_t)(r + 8) * N + cc], acc[mt][nt][2] * i1, acc[mt][nt][3] * i1);
            }
        }
    }
}

// ---------------- fused prep kernel -------------------------------------------
// blocks [0,8192):        x -> fp16  (+ block 0 zeroes rs)
// blocks [8192,11264):    W transposes into Wcat (scale folded into Wq)
// blocks [11264,13312):   zero fp32 out (for split-K red accumulation)
#define PREP_CONV 8192
#define PREP_W    3072
#define PREP_ZERO 2048
__global__ __launch_bounds__(256) void prep_kernel(
    const float* __restrict__ x,
    const float* __restrict__ Wq, const float* __restrict__ Wk,
    const float* __restrict__ Wv,
    __half* __restrict__ xh, __half* __restrict__ Wcat,
    float* __restrict__ rs, float* __restrict__ out)
{
    __shared__ float t[32][33];
    const int bid = blockIdx.x;
    const int tid = threadIdx.x;

    if (bid < PREP_CONV) {
        int i = bid * 256 + tid;                       // 2M float2 elements
        float2 v = reinterpret_cast<const float2*>(x)[i];
        reinterpret_cast<__half2*>(xh)[i] = __floats2half2_rn(v.x, v.y);
        if (bid == 0) {
            for (int j = tid; j < S_DIM; j += 256) rs[j] = 0.0f;
        }
    } else if (bid < PREP_CONV + PREP_W) {
        int b = bid - PREP_CONV;
        int z = b >> 10;                               // 0..2
        int bx = b & 31, by = (b >> 5) & 31;
        const float* W = z == 0 ? Wq : z == 1 ? Wk : Wv;
        const float scale = z == 0 ? 0.03125f : 1.0f;  // 1/sqrt(1024) into Wq
        int tx = tid & 31, ty = tid >> 5;              // 32 x 8
        int xg = bx * 32 + tx;
        int yg = by * 32 + ty;
        #pragma unroll
        for (int j = 0; j < 32; j += 8)
            t[ty + j][tx] = W[(size_t)(yg + j) * D_DIM + xg];
        __syncthreads();
        int x2 = by * 32 + tx;
        int y2 = bx * 32 + ty;
        __half* dst = Wcat + (size_t)z * D_DIM * D_DIM;
        #pragma unroll
        for (int j = 0; j < 32; j += 8)
            dst[(size_t)(y2 + j) * D_DIM + x2] = __float2half(t[tx][ty + j] * scale);
    } else {
        int b = bid - PREP_CONV - PREP_W;              // 0..2047
        float4* o4 = reinterpret_cast<float4*>(out);
        int base = b * 512 + tid;                      // 512 float4 per block
        o4[base]       = make_float4(0.f, 0.f, 0.f, 0.f);
        o4[base + 256] = make_float4(0.f, 0.f, 0.f, 0.f);
    }
}

// ---------------- launch -----------------------------------------------------
extern "C" void kernel_launch(void* const* d_in, const int* in_sizes, int n_in,
                              void* d_out, int out_size)
{
    const float* x  = (const float*)d_in[0];
    const float* Wq = (const float*)d_in[1];
    const float* Wk = (const float*)d_in[2];
    const float* Wv = (const float*)d_in[3];
    float* out = (float*)d_out;

    __half *xh, *Wcat, *Qh, *Kh, *Vh, *Sh;
    float* rs;
    cudaGetSymbolAddress((void**)&xh,   g_xh);
    cudaGetSymbolAddress((void**)&Wcat, g_Wcat);
    cudaGetSymbolAddress((void**)&Qh,   g_Qh);
    cudaGetSymbolAddress((void**)&Kh,   g_Kh);
    cudaGetSymbolAddress((void**)&Vh,   g_Vh);
    cudaGetSymbolAddress((void**)&Sh,   g_Sh);
    cudaGetSymbolAddress((void**)&rs,   g_rs);

    cudaFuncSetAttribute(gemm_f16<0>, cudaFuncAttributeMaxDynamicSharedMemorySize, GSMEM);
    cudaFuncSetAttribute(gemm_f16<2>, cudaFuncAttributeMaxDynamicSharedMemorySize, GSMEM);
    cudaFuncSetAttribute(gemm_f16<3>, cudaFuncAttributeMaxDynamicSharedMemorySize, GSMEM);

    // fused prep: x->fp16, W transposes, rs zero, out zero
    prep_kernel<<<PREP_CONV + PREP_W + PREP_ZERO, 256>>>(x, Wq, Wk, Wv,
                                                         xh, Wcat, rs, out);

    dim3 gemm_blk(128);
    dim3 grid_qkv(3 * D_DIM / 128, S_DIM / 128);      // 24 x 32 = 768 CTAs
    dim3 grid_attn(S_DIM / 128, S_DIM / 128);         // 32 x 32
    dim3 grid_pv(D_DIM / 128, S_DIM / 128, KSPLIT);   // 8 x 32 x 3 = 768 CTAs

    // fused Q/K/V projections (Q pre-scaled via Wcat)
    gemm_f16<2><<<grid_qkv, gemm_blk, GSMEM>>>(xh, Wcat, Qh, Kh, Vh, rs,
                                               S_DIM, 3 * D_DIM, D_DIM);

    // exp(scores) + row sums fused into the GEMM epilogue
    gemm_f16<3><<<grid_attn, gemm_blk, GSMEM>>>(Qh, Kh, Sh, nullptr, nullptr, rs,
                                                S_DIM, S_DIM, D_DIM);

    // context = (P @ V) / rowsum — split-K x3, accumulated with red.global.v2
    gemm_f16<0><<<grid_pv, gemm_blk, GSMEM>>>(Sh, Vh, out, nullptr, nullptr, rs,
                                              S_DIM, D_DIM, S_DIM);
}

// round 15
// speedup vs baseline: 1.0753x; 1.0753x over previous
#include <cuda_runtime.h>
#include <cuda_fp16.h>
#include <cstdint>
#include <cstddef>

#define S_DIM 4096
#define D_DIM 1024

// ---------------- scratch (static device globals; no allocation) -------------
__device__ __half g_xh  [(size_t)S_DIM * D_DIM];
__device__ __half g_Wcat[(size_t)3 * D_DIM * D_DIM];   // [3072,1024] concat Wq^T,Wk^T,Wv^T
__device__ __half g_Qh  [(size_t)S_DIM * D_DIM];
__device__ __half g_Kh  [(size_t)S_DIM * D_DIM];
__device__ __half g_Vh  [(size_t)S_DIM * D_DIM];
__device__ __half g_Sh  [(size_t)S_DIM * S_DIM];       // exp(scores)
__device__ float  g_rs  [S_DIM];                       // row sums of exp(scores)

// ---------------- helpers ----------------------------------------------------
__device__ __forceinline__ uint32_t smem_u32(const void* p) {
    return (uint32_t)__cvta_generic_to_shared(p);
}
__device__ __forceinline__ void cp16(uint32_t dst, const void* src) {
    asm volatile("cp.async.cg.shared.global [%0], [%1], 16;" :: "r"(dst), "l"(src));
}
__device__ __forceinline__ void ldsm_x4(uint32_t& r0, uint32_t& r1,
                                        uint32_t& r2, uint32_t& r3, uint32_t a) {
    asm volatile("ldmatrix.sync.aligned.m8n8.x4.shared.b16 {%0,%1,%2,%3}, [%4];"
                 : "=r"(r0), "=r"(r1), "=r"(r2), "=r"(r3) : "r"(a));
}
__device__ __forceinline__ void ldsm_x4_t(uint32_t& r0, uint32_t& r1,
                                          uint32_t& r2, uint32_t& r3, uint32_t a) {
    asm volatile("ldmatrix.sync.aligned.m8n8.x4.trans.shared.b16 {%0,%1,%2,%3}, [%4];"
                 : "=r"(r0), "=r"(r1), "=r"(r2), "=r"(r3) : "r"(a));
}
__device__ __forceinline__ void mma16816(float* c, const uint32_t* a, const uint32_t* b) {
    asm volatile(
        "mma.sync.aligned.m16n8k16.row.col.f32.f16.f16.f32 "
        "{%0,%1,%2,%3}, {%4,%5,%6,%7}, {%8,%9}, {%0,%1,%2,%3};"
        : "+f"(c[0]), "+f"(c[1]), "+f"(c[2]), "+f"(c[3])
        : "r"(a[0]), "r"(a[1]), "r"(a[2]), "r"(a[3]), "r"(b[0]), "r"(b[1]));
}

// Swizzled byte offset of a 16B segment (row, kseg) in a [rows x 32half] tile.
__device__ __forceinline__ uint32_t tswz(int row, int kseg) {
    return (uint32_t)((row >> 1) * 128 + (row & 1) * 64 +
                      ((((row >> 1) ^ kseg) & 3) << 4));
}

// ---------------- fp16 tensor-core GEMM (R12 mainloop, unchanged) -------------
// MODE 0: C[M,N] = A[M,K] @ B[K,N] (B row-major [K,N], ldmatrix.trans path),
//         fp32 out, rows scaled by 1/RS[row].                      (PV GEMM)
// MODE 2: C = A @ Bt^T, routing - fp16 out to C0/C1/C2 by col0>>10.
// MODE 3: C = A @ Bt^T, fp16 exp(out) + atomic row-sum into RS.    (scores)
#define BKH 32
#define TILE_BYTES 8192            // A: 128r*32k*2B ; B: 32k*128n*2B (same size)
#define STAGE_BYTES (2 * TILE_BYTES)
#define NST 4
#define GSMEM (NST * STAGE_BYTES)  // 64 KB

template <int MODE>
__global__ __launch_bounds__(128, 2) void gemm_f16(
    const __half* __restrict__ A, const __half* __restrict__ Bt,
    void* __restrict__ C0, void* __restrict__ C1, void* __restrict__ C2,
    float* __restrict__ RS, int M, int N, int K)
{
    extern __shared__ char smem[];
    const uint32_t sbase = smem_u32(smem);

    const int tid  = threadIdx.x;
    const int warp = tid >> 5;
    const int lane = tid & 31;
    const int warp_m = warp & 1;    // 2 warps x 64 rows
    const int warp_n = warp >> 1;   // 2 warps x 64 cols
    const int row0 = blockIdx.y * 128;
    const int col0 = blockIdx.x * 128;
    const int NC = K / BKH;

    float acc[4][8][4];
    #pragma unroll
    for (int mt = 0; mt < 4; mt++)
        #pragma unroll
        for (int nt = 0; nt < 8; nt++)
            #pragma unroll
            for (int i = 0; i < 4; i++) acc[mt][nt][i] = 0.0f;

    // ---- per-thread cp.async slots ----
    uint32_t sA[4], sB[4];
    const __half *gA[4], *gB[4];
    #pragma unroll
    for (int p = 0; p < 4; p++) {
        int u = tid + p * 128;
        int r = u >> 2, ks = u & 3;
        sA[p] = tswz(r, ks);
        gA[p] = A + (size_t)(row0 + r) * K + ks * 8;
        if (MODE == 0) {
            int br = u >> 4, nb = u & 15;            // br 0..31, nb 0..15
            sB[p] = TILE_BYTES + br * 256 + ((nb ^ (br & 7)) << 4);
            gB[p] = Bt + (size_t)br * N + col0 + nb * 8;
        } else {
            int br = u >> 2, ks2 = u & 3;
            sB[p] = TILE_BYTES + tswz(br, ks2);
            gB[p] = Bt + (size_t)(col0 + br) * K + ks2 * 8;
        }
    }

    auto load_chunk = [&](int c, int buf) {
        uint32_t base = sbase + buf * STAGE_BYTES;
        size_t offA = (size_t)c * BKH;
        #pragma unroll
        for (int p = 0; p < 4; p++) cp16(base + sA[p], gA[p] + offA);
        if (MODE == 0) {
            size_t offB = (size_t)c * BKH * N;       // advance 32 k-rows
            #pragma unroll
            for (int p = 0; p < 4; p++) cp16(base + sB[p], gB[p] + offB);
        } else {
            #pragma unroll
            for (int p = 0; p < 4; p++) cp16(base + sB[p], gB[p] + offA);
        }
        asm volatile("cp.async.commit_group;");
    };

    load_chunk(0, 0);
    if (NC > 1) load_chunk(1, 1);
    if (NC > 2) load_chunk(2, 2);
    if (NC > 3) load_chunk(3, 3);

    const int lr = lane & 15;
    const int lk = lane >> 4;
    const uint32_t b0_row_off = (uint32_t)(lane & 15) * 256;
    const int b0_xor = lane & 7;
    const int b0_hi = lane >> 4;

    for (int c = 0; c < NC; c++) {
        int buf = c & 3;
        int pend = NC - 1 - c; if (pend > 3) pend = 3;
        if      (pend == 0) asm volatile("cp.async.wait_group 0;");
        else if (pend == 1) asm volatile("cp.async.wait_group 1;");
        else if (pend == 2) asm volatile("cp.async.wait_group 2;");
        else                asm volatile("cp.async.wait_group 3;");
        __syncthreads();

        uint32_t Ab = sbase + buf * STAGE_BYTES;
        uint32_t Bb = Ab + TILE_BYTES;

        #pragma unroll
        for (int ks = 0; ks < 2; ks++) {
            uint32_t af[4][4], blo[8], bhi[8];
            #pragma unroll
            for (int mt = 0; mt < 4; mt++)
                ldsm_x4(af[mt][0], af[mt][1], af[mt][2], af[mt][3],
                        Ab + tswz(warp_m * 64 + mt * 16 + lr, ks * 2 + lk));
            if (MODE == 0) {
                #pragma unroll
                for (int np = 0; np < 4; np++) {
                    int n16 = warp_n * 8 + np * 2 + b0_hi;
                    uint32_t addr = Bb + ks * 4096 + b0_row_off +
                                    (uint32_t)((n16 ^ b0_xor) << 4);
                    ldsm_x4_t(blo[2 * np], bhi[2 * np],
                              blo[2 * np + 1], bhi[2 * np + 1], addr);
                }
            } else {
                #pragma unroll
                for (int np = 0; np < 4; np++)
                    ldsm_x4(blo[2 * np], blo[2 * np + 1], bhi[2 * np], bhi[2 * np + 1],
                            Bb + tswz(warp_n * 64 + np * 16 + lr, ks * 2 + lk));
            }
            #pragma unroll
            for (int mt = 0; mt < 4; mt++)
                #pragma unroll
                for (int nt = 0; nt < 8; nt++) {
                    uint32_t bf[2] = { blo[nt], bhi[nt] };
                    mma16816(acc[mt][nt], af[mt], bf);
                }
        }
        __syncthreads();
        if (c + NST < NC) load_chunk(c + NST, buf);
    }

    // ---- epilogue ----
    const int g = lane >> 2, t = lane & 3;

    if (MODE == 2) {
        int sel = col0 >> 10;
        __half* Ch = (__half*)(sel == 0 ? C0 : sel == 1 ? C1 : C2);
        int cbase = (col0 & 1023) + warp_n * 64;
        #pragma unroll
        for (int mt = 0; mt < 4; mt++) {
            int r = row0 + warp_m * 64 + mt * 16 + g;
            #pragma unroll
            for (int nt = 0; nt < 8; nt++) {
                int cc = cbase + nt * 8 + t * 2;
                *reinterpret_cast<__half2*>(&Ch[(size_t)r * 1024 + cc]) =
                    __floats2half2_rn(acc[mt][nt][0], acc[mt][nt][1]);
                *reinterpret_cast<__half2*>(&Ch[(size_t)(r + 8) * 1024 + cc]) =
                    __floats2half2_rn(acc[mt][nt][2], acc[mt][nt][3]);
            }
        }
    } else if (MODE == 3) {
        __half* Ch = (__half*)C0;
        int cbase = col0 + warp_n * 64;
        #pragma unroll
        for (int mt = 0; mt < 4; mt++) {
            int r = row0 + warp_m * 64 + mt * 16 + g;
            float s0 = 0.0f, s1 = 0.0f;
            #pragma unroll
            for (int nt = 0; nt < 8; nt++) {
                int cc = cbase + nt * 8 + t * 2;
                float e0 = __expf(acc[mt][nt][0]);
                float e1 = __expf(acc[mt][nt][1]);
                float e2 = __expf(acc[mt][nt][2]);
                float e3 = __expf(acc[mt][nt][3]);
                s0 += e0 + e1;
                s1 += e2 + e3;
                *reinterpret_cast<__half2*>(&Ch[(size_t)r * N + cc]) =
                    __floats2half2_rn(e0, e1);
                *reinterpret_cast<__half2*>(&Ch[(size_t)(r + 8) * N + cc]) =
                    __floats2half2_rn(e2, e3);
            }
            s0 += __shfl_xor_sync(0xffffffffu, s0, 1);
            s0 += __shfl_xor_sync(0xffffffffu, s0, 2);
            s1 += __shfl_xor_sync(0xffffffffu, s1, 1);
            s1 += __shfl_xor_sync(0xffffffffu, s1, 2);
            if (t == 0) {
                atomicAdd(&RS[r], s0);
                atomicAdd(&RS[r + 8], s1);
            }
        }
    } else {
        float* Cf = (float*)C0;
        int cbase = col0 + warp_n * 64;
        #pragma unroll
        for (int mt = 0; mt < 4; mt++) {
            int r = row0 + warp_m * 64 + mt * 16 + g;
            float i0 = 1.0f / RS[r];
            float i1 = 1.0f / RS[r + 8];
            #pragma unroll
            for (int nt = 0; nt < 8; nt++) {
                int cc = cbase + nt * 8 + t * 2;
                *reinterpret_cast<float2*>(&Cf[(size_t)r * N + cc]) =
                    make_float2(acc[mt][nt][0] * i0, acc[mt][nt][1] * i0);
                *reinterpret_cast<float2*>(&Cf[(size_t)(r + 8) * N + cc]) =
                    make_float2(acc[mt][nt][2] * i1, acc[mt][nt][3] * i1);
            }
        }
    }
}

// ---------------- fused prep kernel -------------------------------------------
// blocks [0,8192):      x -> fp16  (+ block 0 zeroes rs)
// blocks [8192,11264):  W transposes into Wcat (scale folded into Wq)
#define PREP_CONV 8192
#define PREP_W    3072
__global__ __launch_bounds__(256) void prep_kernel(
    const float* __restrict__ x,
    const float* __restrict__ Wq, const float* __restrict__ Wk,
    const float* __restrict__ Wv,
    __half* __restrict__ xh, __half* __restrict__ Wcat,
    float* __restrict__ rs)
{
    __shared__ float t[32][33];
    const int bid = blockIdx.x;
    const int tid = threadIdx.x;

    if (bid < PREP_CONV) {
        int i = bid * 256 + tid;
        float2 v = reinterpret_cast<const float2*>(x)[i];
        reinterpret_cast<__half2*>(xh)[i] = __floats2half2_rn(v.x, v.y);
        if (bid == 0) {
            for (int j = tid; j < S_DIM; j += 256) rs[j] = 0.0f;
        }
    } else {
        int b = bid - PREP_CONV;
        int z = b >> 10;                               // 0..2
        int bx = b & 31, by = (b >> 5) & 31;
        const float* W = z == 0 ? Wq : z == 1 ? Wk : Wv;
        const float scale = z == 0 ? 0.03125f : 1.0f;  // 1/sqrt(1024) into Wq
        int tx = tid & 31, ty = tid >> 5;              // 32 x 8
        int xg = bx * 32 + tx;
        int yg = by * 32 + ty;
        #pragma unroll
        for (int j = 0; j < 32; j += 8)
            t[ty + j][tx] = W[(size_t)(yg + j) * D_DIM + xg];
        __syncthreads();
        int x2 = by * 32 + tx;
        int y2 = bx * 32 + ty;
        __half* dst = Wcat + (size_t)z * D_DIM * D_DIM;
        #pragma unroll
        for (int j = 0; j < 32; j += 8)
            dst[(size_t)(y2 + j) * D_DIM + x2] = __float2half(t[tx][ty + j] * scale);
    }
}

// ---------------- launch -----------------------------------------------------
extern "C" void kernel_launch(void* const* d_in, const int* in_sizes, int n_in,
                              void* d_out, int out_size)
{
    const float* x  = (const float*)d_in[0];
    const float* Wq = (const float*)d_in[1];
    const float* Wk = (const float*)d_in[2];
    const float* Wv = (const float*)d_in[3];
    float* out = (float*)d_out;

    __half *xh, *Wcat, *Qh, *Kh, *Vh, *Sh;
    float* rs;
    cudaGetSymbolAddress((void**)&xh,   g_xh);
    cudaGetSymbolAddress((void**)&Wcat, g_Wcat);
    cudaGetSymbolAddress((void**)&Qh,   g_Qh);
    cudaGetSymbolAddress((void**)&Kh,   g_Kh);
    cudaGetSymbolAddress((void**)&Vh,   g_Vh);
    cudaGetSymbolAddress((void**)&Sh,   g_Sh);
    cudaGetSymbolAddress((void**)&rs,   g_rs);

    cudaFuncSetAttribute(gemm_f16<0>, cudaFuncAttributeMaxDynamicSharedMemorySize, GSMEM);
    cudaFuncSetAttribute(gemm_f16<2>, cudaFuncAttributeMaxDynamicSharedMemorySize, GSMEM);
    cudaFuncSetAttribute(gemm_f16<3>, cudaFuncAttributeMaxDynamicSharedMemorySize, GSMEM);

    // side stream + fork/join events, created once (capture-compatible)
    static cudaStream_t s2 = nullptr;
    static cudaEvent_t ev_fork = nullptr, ev_join = nullptr;
    if (s2 == nullptr) {
        cudaStreamCreateWithFlags(&s2, cudaStreamNonBlocking);
        cudaEventCreateWithFlags(&ev_fork, cudaEventDisableTiming);
        cudaEventCreateWithFlags(&ev_join, cudaEventDisableTiming);
    }

    // fused prep: x->fp16, W transposes, rs zero
    prep_kernel<<<PREP_CONV + PREP_W, 256>>>(x, Wq, Wk, Wv, xh, Wcat, rs);

    dim3 gemm_blk(128);
    dim3 grid_qk(2 * D_DIM / 128, S_DIM / 128);    // 16 x 32 = 512 CTAs
    dim3 grid_v(D_DIM / 128, S_DIM / 128);         // 8 x 32  = 256 CTAs
    dim3 grid_attn(S_DIM / 128, S_DIM / 128);      // 32 x 32
    dim3 grid_pv(D_DIM / 128, S_DIM / 128);        // 8 x 32

    // fork: V projection on side stream (overlaps QK tail + scores ramp)
    cudaEventRecord(ev_fork, 0);
    cudaStreamWaitEvent(s2, ev_fork, 0);
    gemm_f16<2><<<grid_v, gemm_blk, GSMEM, s2>>>(
        xh, Wcat + (size_t)2 * D_DIM * D_DIM, Vh, nullptr, nullptr, rs,
        S_DIM, D_DIM, D_DIM);

    // Q/K projections on main stream (Q pre-scaled via Wcat)
    gemm_f16<2><<<grid_qk, gemm_blk, GSMEM>>>(xh, Wcat, Qh, Kh, nullptr, rs,
                                              S_DIM, 2 * D_DIM, D_DIM);

    // exp(scores) + row sums fused into the GEMM epilogue
    gemm_f16<3><<<grid_attn, gemm_blk, GSMEM>>>(Qh, Kh, Sh, nullptr, nullptr, rs,
                                                S_DIM, S_DIM, D_DIM);

    // join: PV needs V
    cudaEventRecord(ev_join, s2);
    cudaStreamWaitEvent(0, ev_join, 0);

    // context = (P @ V) / rowsum — V consumed in natural [K,N] layout
    gemm_f16<0><<<grid_pv, gemm_blk, GSMEM>>>(Sh, Vh, out, nullptr, nullptr, rs,
                                              S_DIM, D_DIM, S_DIM);
}